// round 1
// baseline (speedup 1.0000x reference)
#include <cuda_runtime.h>
#include <cstdint>

#define BATCH 16
#define HH 256
#define WW 256
#define CIN 32
#define COUT 32
#define TAPS 9

// Packed ternary-ish weights: w_sum = sum_m sign(W_m) in {-4..4}, stored as int8,
// 4 ci per u32 word for dp4a. Layout [tap][co][j] with j indexing ci-groups of 4.
__device__ uint32_t g_wpk[TAPS][COUT][8];
__device__ float    g_bias[COUT];

// ---------------------------------------------------------------------------
// Prep kernel: build packed weight table + summed bias. Tiny, runs every call
// (deterministic, graph-capturable, no static guards).
// ---------------------------------------------------------------------------
__global__ void prep_kernel(const float* __restrict__ Wt, const float* __restrict__ bias)
{
    int t = threadIdx.x;   // single block, 288 threads
    if (t < TAPS * COUT) {
        int tap = t / COUT;
        int co  = t % COUT;
        #pragma unroll
        for (int j = 0; j < 8; j++) {
            uint32_t word = 0;
            #pragma unroll
            for (int k = 0; k < 4; k++) {
                int ci = j * 4 + k;
                int s = 0;
                #pragma unroll
                for (int m = 0; m < 4; m++) {
                    // W[m, kh, kw, ci, co] flat: ((m*9 + tap)*32 + ci)*32 + co
                    float w = Wt[(((size_t)m * 9 + tap) * 32 + ci) * 32 + co];
                    s += (w >= 0.0f) ? 1 : -1;
                }
                word |= ((uint32_t)(uint8_t)(int8_t)s) << (8 * k);
            }
            g_wpk[tap][co][j] = word;
        }
    }
    if (t < COUT) {
        float s = 0.0f;
        #pragma unroll
        for (int m = 0; m < 4; m++) s += bias[m * COUT + t];
        g_bias[t] = s;
    }
}

// ---------------------------------------------------------------------------
// Conv kernel: one CTA per (image, row). 128 threads, 2 adjacent pixels each.
// x binarized to int8 {+1,-1} packed 4/word in smem (padded cols/rows = 0,
// matching SAME zero-padding of the pre-binarized input). Inner loop: dp4a.
// ---------------------------------------------------------------------------
__device__ __forceinline__ uint32_t pack_sign(float4 v)
{
    uint32_t w;
    w  = (v.x >= 0.0f ? 0x01u : 0xFFu);
    w |= (v.y >= 0.0f ? 0x01u : 0xFFu) << 8;
    w |= (v.z >= 0.0f ? 0x01u : 0xFFu) << 16;
    w |= (v.w >= 0.0f ? 0x01u : 0xFFu) << 24;
    return w;
}

__global__ __launch_bounds__(128)
void conv_kernel(const float* __restrict__ x, float* __restrict__ y)
{
    __shared__ uint32_t sx[3][WW + 2][8];   // 3 rows, 1-pixel pad each side
    __shared__ uint32_t sw[TAPS][COUT][8];
    __shared__ float    sbias[COUT];

    const int tid = threadIdx.x;
    const int row = blockIdx.x;            // 0 .. BATCH*HH-1
    const int h   = row & (HH - 1);
    const int img = row >> 8;

    // Zero entire x tile (covers col pads and out-of-range halo rows)
    for (int i = tid; i < 3 * (WW + 2) * 8; i += 128)
        ((uint32_t*)sx)[i] = 0;
    __syncthreads();

    // Binarize + pack the 3 input rows (h-1, h, h+1)
    for (int r = 0; r < 3; r++) {
        int hh = h - 1 + r;
        if ((unsigned)hh < (unsigned)HH) {
            const float4* src =
                (const float4*)(x + ((size_t)(img * HH + hh) * WW) * CIN);
            for (int i = tid; i < WW * 8; i += 128) {
                int px = i >> 3, j = i & 7;
                sx[r][px + 1][j] = pack_sign(src[(size_t)px * 8 + j]);
            }
        }
    }
    // Stage weights + bias
    for (int i = tid; i < TAPS * COUT * 8; i += 128)
        ((uint32_t*)sw)[i] = ((const uint32_t*)g_wpk)[i];
    if (tid < COUT) sbias[tid] = g_bias[tid];
    __syncthreads();

    const int px0 = tid * 2;

    int acc0[COUT], acc1[COUT];
    #pragma unroll
    for (int co = 0; co < COUT; co++) { acc0[co] = 0; acc1[co] = 0; }

    #pragma unroll 1
    for (int tap = 0; tap < TAPS; tap++) {
        const int kh = tap / 3;
        const int kw = tap - kh * 3;
        // pixel (px0 + kw - 1) in padded coords = px0 + kw ; 32B-aligned
        const uint32_t* xp = &sx[kh][px0 + kw][0];
        const int4 xa0 = *(const int4*)(xp + 0);
        const int4 xa1 = *(const int4*)(xp + 4);
        const int4 xb0 = *(const int4*)(xp + 8);   // second pixel (contiguous)
        const int4 xb1 = *(const int4*)(xp + 12);

        const int4* wp = (const int4*)&sw[tap][0][0];
        #pragma unroll
        for (int co = 0; co < COUT; co++) {
            const int4 w0 = wp[co * 2 + 0];
            const int4 w1 = wp[co * 2 + 1];
            int s0 = acc0[co];
            s0 = __dp4a(xa0.x, w0.x, s0); s0 = __dp4a(xa0.y, w0.y, s0);
            s0 = __dp4a(xa0.z, w0.z, s0); s0 = __dp4a(xa0.w, w0.w, s0);
            s0 = __dp4a(xa1.x, w1.x, s0); s0 = __dp4a(xa1.y, w1.y, s0);
            s0 = __dp4a(xa1.z, w1.z, s0); s0 = __dp4a(xa1.w, w1.w, s0);
            int s1 = acc1[co];
            s1 = __dp4a(xb0.x, w0.x, s1); s1 = __dp4a(xb0.y, w0.y, s1);
            s1 = __dp4a(xb0.z, w0.z, s1); s1 = __dp4a(xb0.w, w0.w, s1);
            s1 = __dp4a(xb1.x, w1.x, s1); s1 = __dp4a(xb1.y, w1.y, s1);
            s1 = __dp4a(xb1.z, w1.z, s1); s1 = __dp4a(xb1.w, w1.w, s1);
            acc0[co] = s0; acc1[co] = s1;
        }
    }

    // Write 2 pixels x 32 couts as float4s
    float4* dst = (float4*)(y + ((size_t)row * WW + px0) * COUT);
    #pragma unroll
    for (int q = 0; q < 8; q++) {
        float4 o;
        o.x = (float)acc0[q * 4 + 0] + sbias[q * 4 + 0];
        o.y = (float)acc0[q * 4 + 1] + sbias[q * 4 + 1];
        o.z = (float)acc0[q * 4 + 2] + sbias[q * 4 + 2];
        o.w = (float)acc0[q * 4 + 3] + sbias[q * 4 + 3];
        dst[q] = o;
    }
    #pragma unroll
    for (int q = 0; q < 8; q++) {
        float4 o;
        o.x = (float)acc1[q * 4 + 0] + sbias[q * 4 + 0];
        o.y = (float)acc1[q * 4 + 1] + sbias[q * 4 + 1];
        o.z = (float)acc1[q * 4 + 2] + sbias[q * 4 + 2];
        o.w = (float)acc1[q * 4 + 3] + sbias[q * 4 + 3];
        dst[8 + q] = o;
    }
}

extern "C" void kernel_launch(void* const* d_in, const int* in_sizes, int n_in,
                              void* d_out, int out_size)
{
    const float* x = (const float*)d_in[0];   // [16,256,256,32]
    const float* W = (const float*)d_in[1];   // [4,3,3,32,32]
    const float* b = (const float*)d_in[2];   // [4,32]
    float* y = (float*)d_out;                 // [16,256,256,32]

    prep_kernel<<<1, TAPS * COUT>>>(W, b);
    conv_kernel<<<BATCH * HH, 128>>>(x, y);
}

// round 3
// speedup vs baseline: 1.2927x; 1.2927x over previous
#include <cuda_runtime.h>
#include <cstdint>

#define BATCH 16
#define HH    256
#define WW    256
#define CIN   32
#define COUT  32
#define TAPS  9

#define RPC      4      // output rows per CTA
#define PXC      128    // pixels per CTA (x-direction)
#define NTHREADS 256

// x smem: 6 rows (RPC + 2 halo) x 132 px x 32B, 16B-chunk swizzled
#define XPX   132
#define ROWB  (XPX * 32)

// B fragments in exact mma order: [ktile(9)][ntile(4)][lane(32)] uint2
__device__ uint2 g_bfrag[TAPS][4][32];
__device__ float g_bias[COUT];

// ---------------------------------------------------------------------------
// Prep: w_sum = sum_m sign(W_m) (int8, in {-4..4}) packed straight into
// mma.m16n8k32 B-fragment order. Also summed bias. Deterministic every call.
// ---------------------------------------------------------------------------
__global__ void prep_kernel(const float* __restrict__ Wt, const float* __restrict__ bias)
{
    const int kt   = blockIdx.x;        // 9 blocks
    const int t    = threadIdx.x;       // 128 threads: nt*32 + lane
    const int nt   = t >> 5;
    const int lane = t & 31;
    const int g    = lane >> 2;         // n within 8
    const int tg   = lane & 3;          // k-byte group
    const int co   = nt * 8 + g;

    uint32_t w0 = 0, w1 = 0;
    #pragma unroll
    for (int j = 0; j < 4; j++) {
        int ci0 = tg * 4 + j;           // k local 0..15 region
        int ci1 = 16 + tg * 4 + j;      // k local 16..31 region
        int s0 = 0, s1 = 0;
        #pragma unroll
        for (int m = 0; m < 4; m++) {
            float a = Wt[((((size_t)m * TAPS + kt) << 5) + ci0) * 32 + co];
            float b = Wt[((((size_t)m * TAPS + kt) << 5) + ci1) * 32 + co];
            s0 += (a >= 0.0f) ? 1 : -1;
            s1 += (b >= 0.0f) ? 1 : -1;
        }
        w0 |= ((uint32_t)(uint8_t)(int8_t)s0) << (8 * j);
        w1 |= ((uint32_t)(uint8_t)(int8_t)s1) << (8 * j);
    }
    g_bfrag[kt][nt][lane] = make_uint2(w0, w1);

    if (kt == 0 && t < COUT) {
        float s = 0.0f;
        #pragma unroll
        for (int m = 0; m < 4; m++) s += bias[m * COUT + t];
        g_bias[t] = s;
    }
}

// sign-pack 4 floats -> 4 int8 bytes in {+1 (0x01), -1 (0xFF)}
__device__ __forceinline__ uint32_t pk4(float4 v)
{
    uint32_t b0 = ((uint32_t)(__float_as_int(v.x) >> 31) & 0xFEu) ^ 1u;
    uint32_t b1 = ((uint32_t)(__float_as_int(v.y) >> 31) & 0xFEu) ^ 1u;
    uint32_t b2 = ((uint32_t)(__float_as_int(v.z) >> 31) & 0xFEu) ^ 1u;
    uint32_t b3 = ((uint32_t)(__float_as_int(v.w) >> 31) & 0xFEu) ^ 1u;
    return b0 | (b1 << 8) | (b2 << 16) | (b3 << 24);
}

__device__ __forceinline__ uint32_t smem_u32(const void* p)
{
    uint32_t a;
    asm("{ .reg .u64 t; cvta.to.shared.u64 t, %1; cvt.u32.u64 %0, t; }" : "=r"(a) : "l"(p));
    return a;
}

// ---------------------------------------------------------------------------
// Conv kernel: implicit GEMM on IMMA (mma.sync m16n8k32 s8)
// ---------------------------------------------------------------------------
__global__ void __launch_bounds__(NTHREADS, 2)
conv_kernel(const float* __restrict__ x, float* __restrict__ y)
{
    __shared__ uint32_t sx[6 * ROWB / 4];          // 6 rows x 132 px x 32B
    __shared__ uint2    sbf[TAPS][4][32];
    __shared__ float    sbias[COUT];

    const int tid  = threadIdx.x;
    const int lane = tid & 31;
    const int wid  = tid >> 5;
    const int bid  = blockIdx.x;
    const int img  = bid >> 7;
    const int rem  = bid & 127;
    const int h0   = (rem >> 1) * RPC;
    const int p0   = (rem & 1) * PXC;

    // ---- stage B fragments + bias ----
    {
        const uint2* src = &g_bfrag[0][0][0];
        uint2*       dst = &sbf[0][0][0];
        for (int i = tid; i < TAPS * 4 * 32; i += NTHREADS) dst[i] = src[i];
    }
    if (tid < COUT) sbias[tid] = g_bias[tid];

    // ---- binarize + pack x: 6 rows x 130 px, unit = 16 floats -> 16B ----
    // smem addr: row*ROWB + spx*32 + ((c ^ ((spx>>2)&1))<<4)
    for (int i = tid; i < 6 * 130 * 2; i += NTHREADS) {
        int u   = i;
        int row = u / 260;
        int j   = u - row * 260;
        int spx = j >> 1;
        int c   = j & 1;
        int hr  = h0 - 1 + row;
        int px  = p0 + spx - 1;
        uint4 v = make_uint4(0, 0, 0, 0);
        if ((unsigned)hr < (unsigned)HH && (unsigned)px < (unsigned)WW) {
            const float4* src = (const float4*)
                (x + (((size_t)(img * HH + hr) * WW + px) << 5) + (c << 4));
            v.x = pk4(src[0]);
            v.y = pk4(src[1]);
            v.z = pk4(src[2]);
            v.w = pk4(src[3]);
        }
        uint32_t off = row * ROWB + spx * 32 + (((uint32_t)c ^ ((uint32_t)(spx >> 2) & 1u)) << 4);
        *(uint4*)((char*)sx + off) = v;
    }
    __syncthreads();

    // ---- warp tile: 64 px x 32 co.  warp w: row r = w>>1, px base = (w&1)*64 ----
    const int r   = wid >> 1;
    const int wpx = (wid & 1) * 64;

    // ldmatrix lane mapping: q = lane>>3: matrices (px0-7,c0)(px8-15,c0)(px0-7,c1)(px8-15,c1)
    const int q      = lane >> 3;
    const int px_off = ((q & 1) << 3) + (lane & 7);
    const int chunk  = q >> 1;

    int acc[4][4][4];
    #pragma unroll
    for (int mt = 0; mt < 4; mt++)
        #pragma unroll
        for (int nt = 0; nt < 4; nt++)
            #pragma unroll
            for (int e = 0; e < 4; e++) acc[mt][nt][e] = 0;

    const uint32_t sx_base = smem_u32(sx);

    #pragma unroll 1
    for (int kt = 0; kt < TAPS; kt++) {
        const int kh = kt / 3;
        const int kw = kt - kh * 3;

        uint2 b[4];
        #pragma unroll
        for (int nt = 0; nt < 4; nt++) b[nt] = sbf[kt][nt][lane];

        const int xrow = (r + kh) * ROWB;

        #pragma unroll
        for (int mt = 0; mt < 4; mt++) {
            const int spx = wpx + mt * 16 + px_off + kw;
            const uint32_t addr = sx_base + xrow + spx * 32 +
                                  (((uint32_t)chunk ^ ((uint32_t)(spx >> 2) & 1u)) << 4);
            uint32_t a0, a1, a2, a3;
            asm volatile("ldmatrix.sync.aligned.m8n8.x4.shared.b16 {%0,%1,%2,%3}, [%4];"
                         : "=r"(a0), "=r"(a1), "=r"(a2), "=r"(a3) : "r"(addr));
            #pragma unroll
            for (int nt = 0; nt < 4; nt++) {
                asm volatile(
                    "mma.sync.aligned.m16n8k32.row.col.s32.s8.s8.s32 "
                    "{%0,%1,%2,%3}, {%4,%5,%6,%7}, {%8,%9}, {%0,%1,%2,%3};"
                    : "+r"(acc[mt][nt][0]), "+r"(acc[mt][nt][1]),
                      "+r"(acc[mt][nt][2]), "+r"(acc[mt][nt][3])
                    : "r"(a0), "r"(a1), "r"(a2), "r"(a3),
                      "r"(b[nt].x), "r"(b[nt].y));
            }
        }
    }

    // ---- epilogue: c-frag (g, 2tg) / (g+8, 2tg) pairs, add bias, STG.64 ----
    const int g  = lane >> 2;
    const int tg = lane & 3;
    const int hrow = img * HH + h0 + r;

    #pragma unroll
    for (int mt = 0; mt < 4; mt++) {
        const int pxa = p0 + wpx + mt * 16 + g;
        float* dsta = y + (((size_t)hrow * WW + pxa) << 5);
        float* dstb = dsta + (8 << 5);
        #pragma unroll
        for (int nt = 0; nt < 4; nt++) {
            const int co = nt * 8 + 2 * tg;
            const float bz0 = sbias[co], bz1 = sbias[co + 1];
            float2 oa, ob;
            oa.x = (float)acc[mt][nt][0] + bz0;
            oa.y = (float)acc[mt][nt][1] + bz1;
            ob.x = (float)acc[mt][nt][2] + bz0;
            ob.y = (float)acc[mt][nt][3] + bz1;
            *(float2*)(dsta + co) = oa;
            *(float2*)(dstb + co) = ob;
        }
    }
}

extern "C" void kernel_launch(void* const* d_in, const int* in_sizes, int n_in,
                              void* d_out, int out_size)
{
    const float* x = (const float*)d_in[0];   // [16,256,256,32]
    const float* W = (const float*)d_in[1];   // [4,3,3,32,32]
    const float* b = (const float*)d_in[2];   // [4,32]
    float* y = (float*)d_out;                 // [16,256,256,32]

    prep_kernel<<<TAPS, 128>>>(W, b);
    conv_kernel<<<BATCH * (HH / RPC) * (WW / PXC), NTHREADS>>>(x, y);
}